// round 3
// baseline (speedup 1.0000x reference)
#include <cuda_runtime.h>
#include <cstddef>

typedef unsigned long long u64;

#define NB 128
#define NS 64
#define NH 32
#define ND 128
#define KPAD 132   // K row stride in floats: 132*4B = 528B -> conflict-free column reads

// ---- packed f32x2 helpers (Blackwell FFMA2 path) ----
__device__ __forceinline__ u64 fma2(u64 a, u64 b, u64 c) {
    u64 d; asm("fma.rn.f32x2 %0, %1, %2, %3;" : "=l"(d) : "l"(a), "l"(b), "l"(c)); return d;
}
__device__ __forceinline__ u64 dup2(float x) {
    u64 d; asm("mov.b64 %0, {%1, %1};" : "=l"(d) : "f"(x), "f"(x)); return d;
}
__device__ __forceinline__ float2 unpk(u64 v) {
    float2 r; asm("mov.b64 {%0, %1}, %2;" : "=f"(r.x), "=f"(r.y) : "l"(v)); return r;
}

// SMEM layout (floats): Q[64][128] | K[64][132] | V[64][128]
// P (softmax probs, duplicated f32x2) reuses the warp's own dead Q rows.
#define SM_Q 0
#define SM_K (NS*ND)
#define SM_V (SM_K + NS*KPAD)
#define SMEM_FLOATS (SM_V + NS*ND)
#define SMEM_BYTES (SMEM_FLOATS * 4)

__global__ __launch_bounds__(256, 2)
void attn_kernel(const float* __restrict__ qkv, const int* __restrict__ kvp,
                 float* __restrict__ out)
{
    extern __shared__ float sm[];
    float* Qs = sm + SM_Q;
    float* Ks = sm + SM_K;
    float* Vs = sm + SM_V;

    const int h    = blockIdx.x & (NH - 1);
    const int b    = blockIdx.x >> 5;
    const int tid  = threadIdx.x;
    const int w    = tid >> 5;
    const int lane = tid & 31;
    const int kvlen = kvp ? *kvp : NS;

    // ---- load phase: coalesced float4 (each warp loads rows w, w+8, ...) ----
    const float* base = qkv + ((size_t)b * NS * NH + h) * (3 * ND);
    for (int r = w; r < NS; r += 8) {
        const float4* src = (const float4*)(base + (size_t)r * (NH * 3 * ND));
        ((float4*)(Qs + r * ND))[lane]   = src[lane];        // Q: d in [0,128)
        ((float4*)(Ks + r * KPAD))[lane] = src[32 + lane];   // K: d in [128,256)
        ((float4*)(Vs + r * ND))[lane]   = src[64 + lane];   // V: d in [256,384)
    }
    __syncthreads();

    const int r0 = w * 8;   // this warp's 8 query rows

    // ---- phase A: scores. acc[r][j] packed (even-d, odd-d) partial sums ----
    u64 acc[8][2];
    #pragma unroll
    for (int r = 0; r < 8; r++) { acc[r][0] = 0ull; acc[r][1] = 0ull; }

    const ulonglong2* k0p = (const ulonglong2*)(Ks + lane * KPAD);          // key = lane
    const ulonglong2* k1p = (const ulonglong2*)(Ks + (lane + 32) * KPAD);   // key = lane+32
    #pragma unroll 4
    for (int d4 = 0; d4 < ND / 4; d4++) {
        ulonglong2 k0 = k0p[d4];
        ulonglong2 k1 = k1p[d4];
        #pragma unroll
        for (int r = 0; r < 8; r++) {
            ulonglong2 q = ((const ulonglong2*)(Qs + (r0 + r) * ND))[d4];  // broadcast
            acc[r][0] = fma2(q.x, k0.x, acc[r][0]);
            acc[r][0] = fma2(q.y, k0.y, acc[r][0]);
            acc[r][1] = fma2(q.x, k1.x, acc[r][1]);
            acc[r][1] = fma2(q.y, k1.y, acc[r][1]);
        }
    }

    // ---- phase B: softmax per row; write duplicated probs into dead Q rows ----
    __syncwarp();   // all lanes done reading this warp's Q rows
    u64* Pw64 = (u64*)(Qs + r0 * ND);   // 512 u64 = 4KB, exactly the warp's Q slice
    const float scale = 0.08838834764831843f;  // 1/sqrt(128)

    #pragma unroll
    for (int r = 0; r < 8; r++) {
        float2 a0 = unpk(acc[r][0]);
        float2 a1 = unpk(acc[r][1]);
        float s0 = (a0.x + a0.y) * scale;
        float s1 = (a1.x + a1.y) * scale;
        if (lane >= kvlen)      s0 = -1e30f;
        if (lane + 32 >= kvlen) s1 = -1e30f;
        float m = fmaxf(s0, s1);
        #pragma unroll
        for (int o = 16; o; o >>= 1) m = fmaxf(m, __shfl_xor_sync(0xffffffffu, m, o));
        float e0 = __expf(s0 - m);
        float e1 = __expf(s1 - m);
        float ss = e0 + e1;
        #pragma unroll
        for (int o = 16; o; o >>= 1) ss += __shfl_xor_sync(0xffffffffu, ss, o);
        float inv = 1.0f / ss;
        // layout: Pw64[k*8 + r], each entry = (p, p) for mov-free f32x2 FMAs
        Pw64[lane * 8 + r]        = dup2(e0 * inv);
        Pw64[(lane + 32) * 8 + r] = dup2(e1 * inv);
    }
    __syncwarp();

    // ---- phase C: O = P @ V. Each lane owns dims [lane*4, lane*4+4). ----
    u64 o[8][2];
    #pragma unroll
    for (int r = 0; r < 8; r++) { o[r][0] = 0ull; o[r][1] = 0ull; }

    #pragma unroll 2
    for (int k = 0; k < NS; k++) {
        ulonglong2 v = ((const ulonglong2*)(Vs + k * ND))[lane];   // 4 V dims
        const ulonglong2* pk = (const ulonglong2*)(Pw64 + k * 8);  // broadcast
        ulonglong2 p01 = pk[0], p23 = pk[1], p45 = pk[2], p67 = pk[3];
        o[0][0] = fma2(p01.x, v.x, o[0][0]);  o[0][1] = fma2(p01.x, v.y, o[0][1]);
        o[1][0] = fma2(p01.y, v.x, o[1][0]);  o[1][1] = fma2(p01.y, v.y, o[1][1]);
        o[2][0] = fma2(p23.x, v.x, o[2][0]);  o[2][1] = fma2(p23.x, v.y, o[2][1]);
        o[3][0] = fma2(p23.y, v.x, o[3][0]);  o[3][1] = fma2(p23.y, v.y, o[3][1]);
        o[4][0] = fma2(p45.x, v.x, o[4][0]);  o[4][1] = fma2(p45.x, v.y, o[4][1]);
        o[5][0] = fma2(p45.y, v.x, o[5][0]);  o[5][1] = fma2(p45.y, v.y, o[5][1]);
        o[6][0] = fma2(p67.x, v.x, o[6][0]);  o[6][1] = fma2(p67.x, v.y, o[6][1]);
        o[7][0] = fma2(p67.y, v.x, o[7][0]);  o[7][1] = fma2(p67.y, v.y, o[7][1]);
    }

    // ---- store: coalesced 128B per warp-row ----
    #pragma unroll
    for (int r = 0; r < 8; r++) {
        ulonglong2 res; res.x = o[r][0]; res.y = o[r][1];
        *(((ulonglong2*)(out + ((size_t)(b * NS + r0 + r) * NH + h) * ND)) + lane) = res;
    }
}

extern "C" void kernel_launch(void* const* d_in, const int* in_sizes, int n_in,
                              void* d_out, int out_size)
{
    const float* qkv  = (const float*)d_in[0];
    const int*   kvlp = (n_in > 1) ? (const int*)d_in[1] : nullptr;
    float*       out  = (float*)d_out;

    cudaFuncSetAttribute(attn_kernel, cudaFuncAttributeMaxDynamicSharedMemorySize, SMEM_BYTES);
    attn_kernel<<<NB * NH, 256, SMEM_BYTES>>>(qkv, kvlp, out);
}

// round 8
// speedup vs baseline: 1.2200x; 1.2200x over previous
#include <cuda_runtime.h>
#include <cuda_bf16.h>
#include <cstdint>
#include <cstddef>

#define QK_SCALE 0.08838834764831843f   // 1/sqrt(128)

// smem: 6 bf16 tiles [64 rows][128 dims], row stride 136 bf16 = 272B.
// 272B = 68 words -> bank start advances by 4 per row -> ldmatrix conflict-free.
#define RSB  272
#define TSZ  (64 * RSB)          // 17408 B per tile
#define T_QH 0
#define T_QL (1 * TSZ)
#define T_KH (2 * TSZ)
#define T_KL (3 * TSZ)
#define T_VH (4 * TSZ)
#define T_VL (5 * TSZ)
#define SMEM_BYTES (6 * TSZ)     // 104448 B -> 2 CTAs/SM

static __device__ __forceinline__ uint32_t smem_u32(const void* p){
    uint32_t a;
    asm("{ .reg .u64 t; cvta.to.shared.u64 t, %1; cvt.u32.u64 %0, t; }" : "=r"(a) : "l"(p));
    return a;
}
// split fp32 pair -> bf16x2 hi (round-to-nearest) + bf16x2 lo (residual)
static __device__ __forceinline__ void split2(float a, float b, uint32_t& hi, uint32_t& lo){
    __nv_bfloat162 h = __floats2bfloat162_rn(a, b);
    float ra = a - __bfloat162float(h.x);
    float rb = b - __bfloat162float(h.y);
    __nv_bfloat162 l = __floats2bfloat162_rn(ra, rb);
    hi = *reinterpret_cast<uint32_t*>(&h);
    lo = *reinterpret_cast<uint32_t*>(&l);
}
static __device__ __forceinline__ void ldsm4(uint32_t* r, uint32_t addr){
    asm volatile("ldmatrix.sync.aligned.m8n8.x4.shared.b16 {%0,%1,%2,%3}, [%4];"
        : "=r"(r[0]), "=r"(r[1]), "=r"(r[2]), "=r"(r[3]) : "r"(addr));
}
static __device__ __forceinline__ void ldsm4t(uint32_t* r, uint32_t addr){
    asm volatile("ldmatrix.sync.aligned.m8n8.x4.trans.shared.b16 {%0,%1,%2,%3}, [%4];"
        : "=r"(r[0]), "=r"(r[1]), "=r"(r[2]), "=r"(r[3]) : "r"(addr));
}
static __device__ __forceinline__ void mma16816(float* c, const uint32_t* a, const uint32_t* b){
    asm volatile("mma.sync.aligned.m16n8k16.row.col.f32.bf16.bf16.f32 "
        "{%0,%1,%2,%3}, {%4,%5,%6,%7}, {%8,%9}, {%0,%1,%2,%3};"
        : "+f"(c[0]), "+f"(c[1]), "+f"(c[2]), "+f"(c[3])
        : "r"(a[0]), "r"(a[1]), "r"(a[2]), "r"(a[3]), "r"(b[0]), "r"(b[1]));
}

__global__ __launch_bounds__(128, 2)
void attn_hmma(const float* __restrict__ qkv, const int* __restrict__ kvp,
               float* __restrict__ out)
{
    extern __shared__ char smem[];
    const uint32_t sb = smem_u32(smem);
    const int tid  = threadIdx.x;
    const int w    = tid >> 5;
    const int lane = tid & 31;
    const int h    = blockIdx.x & 31;
    const int b    = blockIdx.x >> 5;
    const int kvlen = kvp ? *kvp : 64;
    const int q = lane & 3;

    // ---- load + convert: Q*scale, K, V -> bf16 hi/lo smem tiles ----
    for (int r = w; r < 64; r += 4) {
        const float4* src = (const float4*)(qkv + ((size_t)(b * 64 + r) * 32 + h) * 384);
        float4 q4 = src[lane];          // dims 4*lane..+3
        float4 k4 = src[32 + lane];
        float4 v4 = src[64 + lane];
        const uint32_t ro = (uint32_t)(r * RSB + lane * 8);
        uint32_t h0, l0, h1, l1;
        split2(q4.x * QK_SCALE, q4.y * QK_SCALE, h0, l0);
        split2(q4.z * QK_SCALE, q4.w * QK_SCALE, h1, l1);
        *(uint2*)(smem + T_QH + ro) = make_uint2(h0, h1);
        *(uint2*)(smem + T_QL + ro) = make_uint2(l0, l1);
        split2(k4.x, k4.y, h0, l0);
        split2(k4.z, k4.w, h1, l1);
        *(uint2*)(smem + T_KH + ro) = make_uint2(h0, h1);
        *(uint2*)(smem + T_KL + ro) = make_uint2(l0, l1);
        split2(v4.x, v4.y, h0, l0);
        split2(v4.z, v4.w, h1, l1);
        *(uint2*)(smem + T_VH + ro) = make_uint2(h0, h1);
        *(uint2*)(smem + T_VL + ro) = make_uint2(l0, l1);
    }
    __syncthreads();

    // ---- QK^T: warp owns rows [16w,16w+16) x 64 keys; 3 split passes ----
    const int r0 = w * 16;
    float s[8][4];
    #pragma unroll
    for (int nt = 0; nt < 8; nt++)
        #pragma unroll
        for (int j = 0; j < 4; j++) s[nt][j] = 0.0f;

    // A-frag addr: rows r0+(lane&15), dim half via lane bit4
    const uint32_t aQ = sb + (uint32_t)((r0 + (lane & 15)) * RSB + ((lane & 16) ? 16 : 0));
    // B-frag addr (K, non-trans): key part (lane&7)+((lane&16)?8:0), dim half via lane bit3
    const uint32_t bK = sb + (uint32_t)((((lane & 7) + ((lane & 16) ? 8 : 0)) * RSB) + ((lane & 8) ? 16 : 0));

    #pragma unroll
    for (int p = 0; p < 3; p++) {
        const uint32_t At = (p < 2) ? T_QH : T_QL;
        const uint32_t Bt = (p == 1) ? T_KL : T_KH;
        #pragma unroll
        for (int kk = 0; kk < 8; kk++) {
            uint32_t a[4]; ldsm4(a, aQ + At + kk * 32);
            #pragma unroll
            for (int nt2 = 0; nt2 < 4; nt2++) {
                uint32_t bb[4]; ldsm4(bb, bK + Bt + nt2 * (16 * RSB) + kk * 32);
                mma16816(s[2 * nt2],     a, bb);
                mma16816(s[2 * nt2 + 1], a, bb + 2);
            }
        }
    }

    // ---- softmax in C-fragment layout (rows lane/4 and lane/4+8) ----
    float mlo = -3.0e38f, mhi = -3.0e38f;
    #pragma unroll
    for (int nt = 0; nt < 8; nt++) {
        #pragma unroll
        for (int j = 0; j < 4; j++) {
            int col = nt * 8 + q * 2 + (j & 1);
            if (col >= kvlen) s[nt][j] = -3.0e38f;
        }
        mlo = fmaxf(mlo, fmaxf(s[nt][0], s[nt][1]));
        mhi = fmaxf(mhi, fmaxf(s[nt][2], s[nt][3]));
    }
    mlo = fmaxf(mlo, __shfl_xor_sync(0xffffffffu, mlo, 1));
    mlo = fmaxf(mlo, __shfl_xor_sync(0xffffffffu, mlo, 2));
    mhi = fmaxf(mhi, __shfl_xor_sync(0xffffffffu, mhi, 1));
    mhi = fmaxf(mhi, __shfl_xor_sync(0xffffffffu, mhi, 2));

    float slo = 0.0f, shi = 0.0f;
    #pragma unroll
    for (int nt = 0; nt < 8; nt++) {
        s[nt][0] = __expf(s[nt][0] - mlo);
        s[nt][1] = __expf(s[nt][1] - mlo);
        s[nt][2] = __expf(s[nt][2] - mhi);
        s[nt][3] = __expf(s[nt][3] - mhi);
        slo += s[nt][0] + s[nt][1];
        shi += s[nt][2] + s[nt][3];
    }
    slo += __shfl_xor_sync(0xffffffffu, slo, 1);
    slo += __shfl_xor_sync(0xffffffffu, slo, 2);
    shi += __shfl_xor_sync(0xffffffffu, shi, 1);
    shi += __shfl_xor_sync(0xffffffffu, shi, 2);
    const float invlo = 1.0f / slo;
    const float invhi = 1.0f / shi;

    // ---- P (unnormalized) -> A-fragments, hi/lo split. C layout == A layout. ----
    uint32_t ph[4][4], pl[4][4];
    #pragma unroll
    for (int kt = 0; kt < 4; kt++) {
        split2(s[2 * kt][0],     s[2 * kt][1],     ph[kt][0], pl[kt][0]);
        split2(s[2 * kt][2],     s[2 * kt][3],     ph[kt][1], pl[kt][1]);
        split2(s[2 * kt + 1][0], s[2 * kt + 1][1], ph[kt][2], pl[kt][2]);
        split2(s[2 * kt + 1][2], s[2 * kt + 1][3], ph[kt][3], pl[kt][3]);
    }

    // ---- O = P @ V: V row-major, B-frags via ldmatrix.trans; 3 split passes ----
    float o[16][4];
    #pragma unroll
    for (int nt = 0; nt < 16; nt++)
        #pragma unroll
        for (int j = 0; j < 4; j++) o[nt][j] = 0.0f;

    // key part (lane&7)+((lane&8)?8:0), dim-tile half via lane bit4
    const uint32_t bV = sb + (uint32_t)((((lane & 7) + ((lane & 8) ? 8 : 0)) * RSB) + ((lane & 16) ? 16 : 0));

    #pragma unroll
    for (int p = 0; p < 3; p++) {
        const uint32_t Vt = (p == 1) ? T_VL : T_VH;
        const uint32_t (*A)[4] = (p < 2) ? ph : pl;
        #pragma unroll
        for (int kt = 0; kt < 4; kt++) {
            #pragma unroll
            for (int nt2 = 0; nt2 < 8; nt2++) {
                uint32_t bb[4]; ldsm4t(bb, bV + Vt + kt * (16 * RSB) + nt2 * 32);
                mma16816(o[2 * nt2],     A[kt], bb);
                mma16816(o[2 * nt2 + 1], A[kt], bb + 2);
            }
        }
    }

    // ---- store: scale by 1/sum; float2 per n-tile per row ----
    const int rlo = r0 + (lane >> 2);
    float* o0 = out + ((size_t)(b * 64 + rlo) * 32 + h) * 128 + q * 2;
    float* o1 = out + ((size_t)(b * 64 + rlo + 8) * 32 + h) * 128 + q * 2;
    #pragma unroll
    for (int nt = 0; nt < 16; nt++) {
        *(float2*)(o0 + nt * 8) = make_float2(o[nt][0] * invlo, o[nt][1] * invlo);
        *(float2*)(o1 + nt * 8) = make_float2(o[nt][2] * invhi, o[nt][3] * invhi);
    }
}

extern "C" void kernel_launch(void* const* d_in, const int* in_sizes, int n_in,
                              void* d_out, int out_size)
{
    const float* qkv  = (const float*)d_in[0];
    const int*   kvlp = (n_in > 1) ? (const int*)d_in[1] : nullptr;
    float*       out  = (float*)d_out;

    cudaFuncSetAttribute(attn_hmma, cudaFuncAttributeMaxDynamicSharedMemorySize, SMEM_BYTES);
    attn_hmma<<<128 * 32, 128, SMEM_BYTES>>>(qkv, kvlp, out);
}

// round 9
// speedup vs baseline: 1.2557x; 1.0292x over previous
#include <cuda_runtime.h>
#include <cuda_bf16.h>
#include <cstdint>
#include <cstddef>

#define QK_SCALE 0.08838834764831843f   // 1/sqrt(128)

// 4 bf16 tile slots [64 rows][128 dims], row stride 136 bf16 = 272B (conflict-free ldmatrix).
// Phase 1: Qh | Ql | Kh | Kl.  Phase 2: V hi/lo overwrite the dead Q slots.
#define RSB  272
#define TSZ  (64 * RSB)          // 17408 B
#define S_QH 0
#define S_QL (1 * TSZ)
#define S_KH (2 * TSZ)
#define S_KL (3 * TSZ)
#define S_VH 0
#define S_VL (1 * TSZ)
#define SMEM_BYTES (4 * TSZ)     // 69632 B -> 3 CTAs/SM

static __device__ __forceinline__ uint32_t smem_u32(const void* p){
    uint32_t a;
    asm("{ .reg .u64 t; cvta.to.shared.u64 t, %1; cvt.u32.u64 %0, t; }" : "=r"(a) : "l"(p));
    return a;
}
// split fp32 pair -> bf16x2 hi (RN) + bf16x2 lo (residual)
static __device__ __forceinline__ void split2(float a, float b, uint32_t& hi, uint32_t& lo){
    __nv_bfloat162 h = __floats2bfloat162_rn(a, b);
    float ra = a - __bfloat162float(h.x);
    float rb = b - __bfloat162float(h.y);
    __nv_bfloat162 l = __floats2bfloat162_rn(ra, rb);
    hi = *reinterpret_cast<uint32_t*>(&h);
    lo = *reinterpret_cast<uint32_t*>(&l);
}
static __device__ __forceinline__ void ldsm4(uint32_t* r, uint32_t addr){
    asm volatile("ldmatrix.sync.aligned.m8n8.x4.shared.b16 {%0,%1,%2,%3}, [%4];"
        : "=r"(r[0]), "=r"(r[1]), "=r"(r[2]), "=r"(r[3]) : "r"(addr));
}
static __device__ __forceinline__ void ldsm4t(uint32_t* r, uint32_t addr){
    asm volatile("ldmatrix.sync.aligned.m8n8.x4.trans.shared.b16 {%0,%1,%2,%3}, [%4];"
        : "=r"(r[0]), "=r"(r[1]), "=r"(r[2]), "=r"(r[3]) : "r"(addr));
}
static __device__ __forceinline__ void mma16816(float* c, const uint32_t* a, const uint32_t* b){
    asm volatile("mma.sync.aligned.m16n8k16.row.col.f32.bf16.bf16.f32 "
        "{%0,%1,%2,%3}, {%4,%5,%6,%7}, {%8,%9}, {%0,%1,%2,%3};"
        : "+f"(c[0]), "+f"(c[1]), "+f"(c[2]), "+f"(c[3])
        : "r"(a[0]), "r"(a[1]), "r"(a[2]), "r"(a[3]), "r"(b[0]), "r"(b[1]));
}

__global__ __launch_bounds__(128, 3)
void attn_hmma(const float* __restrict__ qkv, const int* __restrict__ kvp,
               float* __restrict__ out)
{
    extern __shared__ char smem[];
    const uint32_t sb = smem_u32(smem);
    const int tid  = threadIdx.x;
    const int w    = tid >> 5;
    const int lane = tid & 31;
    const int h    = blockIdx.x & 31;
    const int b    = blockIdx.x >> 5;
    const int kvlen = kvp ? *kvp : 64;
    const int q = lane & 3;

    // ---- phase 1: load + convert Q*scale, K -> bf16 hi/lo tiles ----
    for (int r = w; r < 64; r += 4) {
        const float4* src = (const float4*)(qkv + ((size_t)(b * 64 + r) * 32 + h) * 384);
        float4 q4 = src[lane];          // Q dims 4*lane..+3
        float4 k4 = src[32 + lane];     // K dims
        const uint32_t ro = (uint32_t)(r * RSB + lane * 8);
        uint32_t h0, l0, h1, l1;
        split2(q4.x * QK_SCALE, q4.y * QK_SCALE, h0, l0);
        split2(q4.z * QK_SCALE, q4.w * QK_SCALE, h1, l1);
        *(uint2*)(smem + S_QH + ro) = make_uint2(h0, h1);
        *(uint2*)(smem + S_QL + ro) = make_uint2(l0, l1);
        split2(k4.x, k4.y, h0, l0);
        split2(k4.z, k4.w, h1, l1);
        *(uint2*)(smem + S_KH + ro) = make_uint2(h0, h1);
        *(uint2*)(smem + S_KL + ro) = make_uint2(l0, l1);
    }
    __syncthreads();

    // ---- QK^T: warp owns rows [16w,16w+16) x 64 keys, 3 bf16-split passes ----
    const int r0 = w * 16;
    float s[8][4];
    #pragma unroll
    for (int nt = 0; nt < 8; nt++)
        #pragma unroll
        for (int j = 0; j < 4; j++) s[nt][j] = 0.0f;

    // A-frag: rows r0+(lane&15), dim half via lane bit4
    const uint32_t aQ = sb + (uint32_t)((r0 + (lane & 15)) * RSB + ((lane & 16) ? 16 : 0));
    // B-frag (K, non-trans): key (lane&7)+((lane&16)?8:0), dim half via lane bit3
    const uint32_t bK = sb + (uint32_t)((((lane & 7) + ((lane & 16) ? 8 : 0)) * RSB) + ((lane & 8) ? 16 : 0));

    #pragma unroll
    for (int kk = 0; kk < 8; kk++) {
        uint32_t ah[4], al[4];
        ldsm4(ah, aQ + S_QH + kk * 32);
        ldsm4(al, aQ + S_QL + kk * 32);
        #pragma unroll
        for (int nt2 = 0; nt2 < 4; nt2++) {
            uint32_t bh[4], bl[4];
            ldsm4(bh, bK + S_KH + nt2 * (16 * RSB) + kk * 32);
            ldsm4(bl, bK + S_KL + nt2 * (16 * RSB) + kk * 32);
            mma16816(s[2*nt2],   ah, bh);  mma16816(s[2*nt2+1], ah, bh + 2);
            mma16816(s[2*nt2],   ah, bl);  mma16816(s[2*nt2+1], ah, bl + 2);
            mma16816(s[2*nt2],   al, bh);  mma16816(s[2*nt2+1], al, bh + 2);
        }
    }

    // ---- softmax in C-fragment layout (rows lane/4 and lane/4+8) ----
    float mlo = -3.0e38f, mhi = -3.0e38f;
    #pragma unroll
    for (int nt = 0; nt < 8; nt++) {
        #pragma unroll
        for (int j = 0; j < 4; j++) {
            int col = nt * 8 + q * 2 + (j & 1);
            if (col >= kvlen) s[nt][j] = -3.0e38f;
        }
        mlo = fmaxf(mlo, fmaxf(s[nt][0], s[nt][1]));
        mhi = fmaxf(mhi, fmaxf(s[nt][2], s[nt][3]));
    }
    mlo = fmaxf(mlo, __shfl_xor_sync(0xffffffffu, mlo, 1));
    mlo = fmaxf(mlo, __shfl_xor_sync(0xffffffffu, mlo, 2));
    mhi = fmaxf(mhi, __shfl_xor_sync(0xffffffffu, mhi, 1));
    mhi = fmaxf(mhi, __shfl_xor_sync(0xffffffffu, mhi, 2));

    float slo = 0.0f, shi = 0.0f;
    #pragma unroll
    for (int nt = 0; nt < 8; nt++) {
        s[nt][0] = __expf(s[nt][0] - mlo);
        s[nt][1] = __expf(s[nt][1] - mlo);
        s[nt][2] = __expf(s[nt][2] - mhi);
        s[nt][3] = __expf(s[nt][3] - mhi);
        slo += s[nt][0] + s[nt][1];
        shi += s[nt][2] + s[nt][3];
    }
    slo += __shfl_xor_sync(0xffffffffu, slo, 1);
    slo += __shfl_xor_sync(0xffffffffu, slo, 2);
    shi += __shfl_xor_sync(0xffffffffu, shi, 1);
    shi += __shfl_xor_sync(0xffffffffu, shi, 2);
    const float invlo = 1.0f / slo;
    const float invhi = 1.0f / shi;

    // ---- P (unnormalized) -> A-fragments hi/lo (C layout == A layout); s dies here ----
    uint32_t ph[4][4], pl[4][4];
    #pragma unroll
    for (int kt = 0; kt < 4; kt++) {
        split2(s[2*kt][0],   s[2*kt][1],   ph[kt][0], pl[kt][0]);
        split2(s[2*kt][2],   s[2*kt][3],   ph[kt][1], pl[kt][1]);
        split2(s[2*kt+1][0], s[2*kt+1][1], ph[kt][2], pl[kt][2]);
        split2(s[2*kt+1][2], s[2*kt+1][3], ph[kt][3], pl[kt][3]);
    }

    // ---- phase 2: V load + convert into dead Q slots ----
    __syncthreads();   // everyone done reading Q tiles
    for (int r = w; r < 64; r += 4) {
        const float4* src = (const float4*)(qkv + ((size_t)(b * 64 + r) * 32 + h) * 384);
        float4 v4 = src[64 + lane];
        const uint32_t ro = (uint32_t)(r * RSB + lane * 8);
        uint32_t h0, l0, h1, l1;
        split2(v4.x, v4.y, h0, l0);
        split2(v4.z, v4.w, h1, l1);
        *(uint2*)(smem + S_VH + ro) = make_uint2(h0, h1);
        *(uint2*)(smem + S_VL + ro) = make_uint2(l0, l1);
    }
    __syncthreads();

    // ---- O = P @ V in two 64-dim halves (accumulators 32 regs each) ----
    // B-frag (V, trans): key (lane&7)+((lane&8)?8:0), 8-dim half via lane bit4
    const uint32_t bV = sb + (uint32_t)((((lane & 7) + ((lane & 8) ? 8 : 0)) * RSB) + ((lane & 16) ? 16 : 0));
    const int rlo = r0 + (lane >> 2);
    float* o0 = out + ((size_t)(b * 64 + rlo) * 32 + h) * 128 + q * 2;
    float* o1 = out + ((size_t)(b * 64 + rlo + 8) * 32 + h) * 128 + q * 2;

    #pragma unroll
    for (int hd = 0; hd < 2; hd++) {
        float o[8][4];
        #pragma unroll
        for (int nt = 0; nt < 8; nt++)
            #pragma unroll
            for (int j = 0; j < 4; j++) o[nt][j] = 0.0f;

        #pragma unroll
        for (int kt = 0; kt < 4; kt++) {
            #pragma unroll
            for (int nt2 = 0; nt2 < 4; nt2++) {
                uint32_t bh[4], bl[4];
                const uint32_t voff = (uint32_t)(kt * (16 * RSB) + hd * 128 + nt2 * 32);
                ldsm4t(bh, bV + S_VH + voff);
                ldsm4t(bl, bV + S_VL + voff);
                mma16816(o[2*nt2],   ph[kt], bh);  mma16816(o[2*nt2+1], ph[kt], bh + 2);
                mma16816(o[2*nt2],   ph[kt], bl);  mma16816(o[2*nt2+1], ph[kt], bl + 2);
                mma16816(o[2*nt2],   pl[kt], bh);  mma16816(o[2*nt2+1], pl[kt], bh + 2);
            }
        }
        #pragma unroll
        for (int nt = 0; nt < 8; nt++) {
            *(float2*)(o0 + hd * 64 + nt * 8) = make_float2(o[nt][0] * invlo, o[nt][1] * invlo);
            *(float2*)(o1 + hd * 64 + nt * 8) = make_float2(o[nt][2] * invhi, o[nt][3] * invhi);
        }
    }
}

extern "C" void kernel_launch(void* const* d_in, const int* in_sizes, int n_in,
                              void* d_out, int out_size)
{
    const float* qkv  = (const float*)d_in[0];
    const int*   kvlp = (n_in > 1) ? (const int*)d_in[1] : nullptr;
    float*       out  = (float*)d_out;

    cudaFuncSetAttribute(attn_hmma, cudaFuncAttributeMaxDynamicSharedMemorySize, SMEM_BYTES);
    attn_hmma<<<128 * 32, 128, SMEM_BYTES>>>(qkv, kvlp, out);
}

// round 10
// speedup vs baseline: 1.6268x; 1.2956x over previous
#include <cuda_runtime.h>
#include <cuda_bf16.h>
#include <cstdint>
#include <cstddef>

#define QK_SCALE 0.08838834764831843f   // 1/sqrt(128)

// 2 bf16 tile slots [64 rows][128 dims], row stride 136 bf16 = 272B (conflict-free ldmatrix).
// Phase 1: Kh | Kl.  Phase 2: V hi/lo overwrite the same slots.
#define RSB  272
#define TSZ  (64 * RSB)          // 17408 B
#define S_KH 0
#define S_KL (1 * TSZ)
#define S_VH 0
#define S_VL (1 * TSZ)
#define SMEM_BYTES (2 * TSZ)     // 34816 B -> up to 5 CTAs/SM

static __device__ __forceinline__ uint32_t smem_u32(const void* p){
    uint32_t a;
    asm("{ .reg .u64 t; cvta.to.shared.u64 t, %1; cvt.u32.u64 %0, t; }" : "=r"(a) : "l"(p));
    return a;
}
// split fp32 pair -> bf16x2 hi (RN) + bf16x2 lo (residual)
static __device__ __forceinline__ void split2(float a, float b, uint32_t& hi, uint32_t& lo){
    __nv_bfloat162 h = __floats2bfloat162_rn(a, b);
    float ra = a - __bfloat162float(h.x);
    float rb = b - __bfloat162float(h.y);
    __nv_bfloat162 l = __floats2bfloat162_rn(ra, rb);
    hi = *reinterpret_cast<uint32_t*>(&h);
    lo = *reinterpret_cast<uint32_t*>(&l);
}
static __device__ __forceinline__ void ldsm4(uint32_t* r, uint32_t addr){
    asm volatile("ldmatrix.sync.aligned.m8n8.x4.shared.b16 {%0,%1,%2,%3}, [%4];"
        : "=r"(r[0]), "=r"(r[1]), "=r"(r[2]), "=r"(r[3]) : "r"(addr));
}
static __device__ __forceinline__ void ldsm4t(uint32_t* r, uint32_t addr){
    asm volatile("ldmatrix.sync.aligned.m8n8.x4.trans.shared.b16 {%0,%1,%2,%3}, [%4];"
        : "=r"(r[0]), "=r"(r[1]), "=r"(r[2]), "=r"(r[3]) : "r"(addr));
}
static __device__ __forceinline__ void mma16816(float* c, const uint32_t* a, const uint32_t* b){
    asm volatile("mma.sync.aligned.m16n8k16.row.col.f32.bf16.bf16.f32 "
        "{%0,%1,%2,%3}, {%4,%5,%6,%7}, {%8,%9}, {%0,%1,%2,%3};"
        : "+f"(c[0]), "+f"(c[1]), "+f"(c[2]), "+f"(c[3])
        : "r"(a[0]), "r"(a[1]), "r"(a[2]), "r"(a[3]), "r"(b[0]), "r"(b[1]));
}

__global__ __launch_bounds__(128, 5)
void attn_hmma(const float* __restrict__ qkv, const int* __restrict__ kvp,
               float* __restrict__ out)
{
    extern __shared__ char smem[];
    const uint32_t sb = smem_u32(smem);
    const int tid  = threadIdx.x;
    const int w    = tid >> 5;
    const int lane = tid & 31;
    const int h    = blockIdx.x & 31;
    const int b    = blockIdx.x >> 5;
    const int kvlen = kvp ? *kvp : 64;
    const int q = lane & 3;

    // ---- phase 1: load + convert K -> bf16 hi/lo tiles (Q stays in gmem) ----
    for (int r = w; r < 64; r += 4) {
        const float4* src = (const float4*)(qkv + ((size_t)(b * 64 + r) * 32 + h) * 384);
        float4 k4 = src[32 + lane];     // K dims 4*lane..+3
        const uint32_t ro = (uint32_t)(r * RSB + lane * 8);
        uint32_t h0, l0, h1, l1;
        split2(k4.x, k4.y, h0, l0);
        split2(k4.z, k4.w, h1, l1);
        *(uint2*)(smem + S_KH + ro) = make_uint2(h0, h1);
        *(uint2*)(smem + S_KL + ro) = make_uint2(l0, l1);
    }
    __syncthreads();

    // ---- QK^T: warp owns rows [16w,16w+16) x 64 keys, 3 bf16-split passes ----
    // Q A-fragments loaded directly from gmem, one kk-tile ahead.
    const int r0 = w * 16;
    const int ra = r0 + (lane >> 2);            // frag rows ra, ra+8
    const float* qrowA = qkv + ((size_t)(b * 64 + ra) * 32 + h) * 384 + q * 2;
    const float* qrowB = qrowA + (size_t)8 * 32 * 384;   // row ra+8

    float s[8][4];
    #pragma unroll
    for (int nt = 0; nt < 8; nt++)
        #pragma unroll
        for (int j = 0; j < 4; j++) s[nt][j] = 0.0f;

    // B-frag (K, non-trans): key (lane&7)+((lane&16)?8:0), dim half via lane bit3
    const uint32_t bK = sb + (uint32_t)((((lane & 7) + ((lane & 16) ? 8 : 0)) * RSB) + ((lane & 8) ? 16 : 0));

    float2 x0 = *(const float2*)(qrowA + 0);        // (ra,   c)
    float2 x1 = *(const float2*)(qrowB + 0);        // (ra+8, c)
    float2 x2 = *(const float2*)(qrowA + 8);        // (ra,   c+8)
    float2 x3 = *(const float2*)(qrowB + 8);        // (ra+8, c+8)

    #pragma unroll
    for (int kk = 0; kk < 8; kk++) {
        uint32_t ah[4], al[4];
        split2(x0.x * QK_SCALE, x0.y * QK_SCALE, ah[0], al[0]);
        split2(x1.x * QK_SCALE, x1.y * QK_SCALE, ah[1], al[1]);
        split2(x2.x * QK_SCALE, x2.y * QK_SCALE, ah[2], al[2]);
        split2(x3.x * QK_SCALE, x3.y * QK_SCALE, ah[3], al[3]);
        if (kk < 7) {
            const int d = (kk + 1) * 16;
            x0 = *(const float2*)(qrowA + d);
            x1 = *(const float2*)(qrowB + d);
            x2 = *(const float2*)(qrowA + d + 8);
            x3 = *(const float2*)(qrowB + d + 8);
        }
        #pragma unroll
        for (int nt2 = 0; nt2 < 4; nt2++) {
            uint32_t bh[4], bl[4];
            ldsm4(bh, bK + S_KH + nt2 * (16 * RSB) + kk * 32);
            ldsm4(bl, bK + S_KL + nt2 * (16 * RSB) + kk * 32);
            mma16816(s[2*nt2],   ah, bh);  mma16816(s[2*nt2+1], ah, bh + 2);
            mma16816(s[2*nt2],   ah, bl);  mma16816(s[2*nt2+1], ah, bl + 2);
            mma16816(s[2*nt2],   al, bh);  mma16816(s[2*nt2+1], al, bh + 2);
        }
    }

    // ---- softmax in C-fragment layout (rows lane/4 and lane/4+8) ----
    float mlo = -3.0e38f, mhi = -3.0e38f;
    #pragma unroll
    for (int nt = 0; nt < 8; nt++) {
        #pragma unroll
        for (int j = 0; j < 4; j++) {
            int col = nt * 8 + q * 2 + (j & 1);
            if (col >= kvlen) s[nt][j] = -3.0e38f;
        }
        mlo = fmaxf(mlo, fmaxf(s[nt][0], s[nt][1]));
        mhi = fmaxf(mhi, fmaxf(s[nt][2], s[nt][3]));
    }
    mlo = fmaxf(mlo, __shfl_xor_sync(0xffffffffu, mlo, 1));
    mlo = fmaxf(mlo, __shfl_xor_sync(0xffffffffu, mlo, 2));
    mhi = fmaxf(mhi, __shfl_xor_sync(0xffffffffu, mhi, 1));
    mhi = fmaxf(mhi, __shfl_xor_sync(0xffffffffu, mhi, 2));

    float slo = 0.0f, shi = 0.0f;
    #pragma unroll
    for (int nt = 0; nt < 8; nt++) {
        s[nt][0] = __expf(s[nt][0] - mlo);
        s[nt][1] = __expf(s[nt][1] - mlo);
        s[nt][2] = __expf(s[nt][2] - mhi);
        s[nt][3] = __expf(s[nt][3] - mhi);
        slo += s[nt][0] + s[nt][1];
        shi += s[nt][2] + s[nt][3];
    }
    slo += __shfl_xor_sync(0xffffffffu, slo, 1);
    slo += __shfl_xor_sync(0xffffffffu, slo, 2);
    shi += __shfl_xor_sync(0xffffffffu, shi, 1);
    shi += __shfl_xor_sync(0xffffffffu, shi, 2);
    const float invlo = 1.0f / slo;
    const float invhi = 1.0f / shi;

    // ---- P (unnormalized) -> A-fragments hi/lo (C layout == A layout) ----
    uint32_t ph[4][4], pl[4][4];
    #pragma unroll
    for (int kt = 0; kt < 4; kt++) {
        split2(s[2*kt][0],   s[2*kt][1],   ph[kt][0], pl[kt][0]);
        split2(s[2*kt][2],   s[2*kt][3],   ph[kt][1], pl[kt][1]);
        split2(s[2*kt+1][0], s[2*kt+1][1], ph[kt][2], pl[kt][2]);
        split2(s[2*kt+1][2], s[2*kt+1][3], ph[kt][3], pl[kt][3]);
    }

    // ---- phase 2: V load + convert into the (dead) K slots ----
    __syncthreads();   // all warps done reading K tiles
    for (int r = w; r < 64; r += 4) {
        const float4* src = (const float4*)(qkv + ((size_t)(b * 64 + r) * 32 + h) * 384);
        float4 v4 = src[64 + lane];
        const uint32_t ro = (uint32_t)(r * RSB + lane * 8);
        uint32_t h0, l0, h1, l1;
        split2(v4.x, v4.y, h0, l0);
        split2(v4.z, v4.w, h1, l1);
        *(uint2*)(smem + S_VH + ro) = make_uint2(h0, h1);
        *(uint2*)(smem + S_VL + ro) = make_uint2(l0, l1);
    }
    __syncthreads();

    // ---- O = P @ V in two 64-dim halves (accumulators 32 regs each) ----
    // B-frag (V, trans): key (lane&7)+((lane&8)?8:0), 8-dim half via lane bit4
    const uint32_t bV = sb + (uint32_t)((((lane & 7) + ((lane & 8) ? 8 : 0)) * RSB) + ((lane & 16) ? 16 : 0));
    float* o0 = out + ((size_t)(b * 64 + ra) * 32 + h) * 128 + q * 2;
    float* o1 = out + ((size_t)(b * 64 + ra + 8) * 32 + h) * 128 + q * 2;

    #pragma unroll
    for (int hd = 0; hd < 2; hd++) {
        float o[8][4];
        #pragma unroll
        for (int nt = 0; nt < 8; nt++)
            #pragma unroll
            for (int j = 0; j < 4; j++) o[nt][j] = 0.0f;

        #pragma unroll
        for (int kt = 0; kt < 4; kt++) {
            #pragma unroll
            for (int nt2 = 0; nt2 < 4; nt2++) {
                uint32_t bh[4], bl[4];
                const uint32_t voff = (uint32_t)(kt * (16 * RSB) + hd * 128 + nt2 * 32);
                ldsm4t(bh, bV + S_VH + voff);
                ldsm4t(bl, bV + S_VL + voff);
                mma16816(o[2*nt2],   ph[kt], bh);  mma16816(o[2*nt2+1], ph[kt], bh + 2);
                mma16816(o[2*nt2],   ph[kt], bl);  mma16816(o[2*nt2+1], ph[kt], bl + 2);
                mma16816(o[2*nt2],   pl[kt], bh);  mma16816(o[2*nt2+1], pl[kt], bh + 2);
            }
        }
        #pragma unroll
        for (int nt = 0; nt < 8; nt++) {
            *(float2*)(o0 + hd * 64 + nt * 8) = make_float2(o[nt][0] * invlo, o[nt][1] * invlo);
            *(float2*)(o1 + hd * 64 + nt * 8) = make_float2(o[nt][2] * invhi, o[nt][3] * invhi);
        }
    }
}

extern "C" void kernel_launch(void* const* d_in, const int* in_sizes, int n_in,
                              void* d_out, int out_size)
{
    const float* qkv  = (const float*)d_in[0];
    const int*   kvlp = (n_in > 1) ? (const int*)d_in[1] : nullptr;
    float*       out  = (float*)d_out;

    cudaFuncSetAttribute(attn_hmma, cudaFuncAttributeMaxDynamicSharedMemorySize, SMEM_BYTES);
    attn_hmma<<<128 * 32, 128, SMEM_BYTES>>>(qkv, kvlp, out);
}

// round 11
// speedup vs baseline: 2.7161x; 1.6696x over previous
#include <cuda_runtime.h>
#include <cuda_fp16.h>
#include <cstdint>
#include <cstddef>

#define QK_SCALE 0.08838834764831843f   // 1/sqrt(128)

// ONE fp16 tile slot [64 rows][128 dims], row stride 136 halves = 272B
// (bank start advances 4 words/row -> conflict-free ldmatrix).
// Phase 1: K.  Phase 2 (after QK): V overwrites it.
#define RSB  272
#define SMEM_BYTES (64 * RSB)    // 17408 B

static __device__ __forceinline__ uint32_t smem_u32(const void* p){
    uint32_t a;
    asm("{ .reg .u64 t; cvta.to.shared.u64 t, %1; cvt.u32.u64 %0, t; }" : "=r"(a) : "l"(p));
    return a;
}
static __device__ __forceinline__ uint32_t h2(float a, float b){
    __half2 h = __floats2half2_rn(a, b);
    return *reinterpret_cast<uint32_t*>(&h);
}
static __device__ __forceinline__ void ldsm4(uint32_t* r, uint32_t addr){
    asm volatile("ldmatrix.sync.aligned.m8n8.x4.shared.b16 {%0,%1,%2,%3}, [%4];"
        : "=r"(r[0]), "=r"(r[1]), "=r"(r[2]), "=r"(r[3]) : "r"(addr));
}
static __device__ __forceinline__ void ldsm4t(uint32_t* r, uint32_t addr){
    asm volatile("ldmatrix.sync.aligned.m8n8.x4.trans.shared.b16 {%0,%1,%2,%3}, [%4];"
        : "=r"(r[0]), "=r"(r[1]), "=r"(r[2]), "=r"(r[3]) : "r"(addr));
}
static __device__ __forceinline__ void mma16816(float* c, const uint32_t* a, const uint32_t* b){
    asm volatile("mma.sync.aligned.m16n8k16.row.col.f32.f16.f16.f32 "
        "{%0,%1,%2,%3}, {%4,%5,%6,%7}, {%8,%9}, {%0,%1,%2,%3};"
        : "+f"(c[0]), "+f"(c[1]), "+f"(c[2]), "+f"(c[3])
        : "r"(a[0]), "r"(a[1]), "r"(a[2]), "r"(a[3]), "r"(b[0]), "r"(b[1]));
}

__global__ __launch_bounds__(128, 6)
void attn_hmma(const float* __restrict__ qkv, const int* __restrict__ kvp,
               float* __restrict__ out)
{
    extern __shared__ char smem[];
    const uint32_t sb = smem_u32(smem);
    const int tid  = threadIdx.x;
    const int w    = tid >> 5;
    const int lane = tid & 31;
    const int h    = blockIdx.x & 31;
    const int b    = blockIdx.x >> 5;
    const int kvlen = kvp ? *kvp : 64;
    const int q = lane & 3;

    // ---- phase 1: K -> fp16 smem tile (Q stays in gmem) ----
    #pragma unroll 4
    for (int r = w; r < 64; r += 4) {
        const float4* src = (const float4*)(qkv + ((size_t)(b * 64 + r) * 32 + h) * 384);
        float4 k4 = src[32 + lane];     // K dims 4*lane..+3
        *(uint2*)(smem + r * RSB + lane * 8) = make_uint2(h2(k4.x, k4.y), h2(k4.z, k4.w));
    }
    __syncthreads();

    // ---- QK^T: warp owns rows [16w,16w+16) x 64 keys, single fp16 pass ----
    const int r0 = w * 16;
    const int ra = r0 + (lane >> 2);            // frag rows ra, ra+8
    const float* qrowA = qkv + ((size_t)(b * 64 + ra) * 32 + h) * 384 + q * 2;
    const float* qrowB = qrowA + (size_t)8 * 32 * 384;   // row ra+8

    float s[8][4];
    #pragma unroll
    for (int nt = 0; nt < 8; nt++)
        #pragma unroll
        for (int j = 0; j < 4; j++) s[nt][j] = 0.0f;

    // B-frag (K, non-trans): key (lane&7)+((lane&16)?8:0), dim half via lane bit3
    const uint32_t bK = sb + (uint32_t)((((lane & 7) + ((lane & 16) ? 8 : 0)) * RSB) + ((lane & 8) ? 16 : 0));

    float2 x0 = *(const float2*)(qrowA + 0);
    float2 x1 = *(const float2*)(qrowB + 0);
    float2 x2 = *(const float2*)(qrowA + 8);
    float2 x3 = *(const float2*)(qrowB + 8);

    #pragma unroll
    for (int kk = 0; kk < 8; kk++) {
        uint32_t a[4];
        a[0] = h2(x0.x * QK_SCALE, x0.y * QK_SCALE);
        a[1] = h2(x1.x * QK_SCALE, x1.y * QK_SCALE);
        a[2] = h2(x2.x * QK_SCALE, x2.y * QK_SCALE);
        a[3] = h2(x3.x * QK_SCALE, x3.y * QK_SCALE);
        if (kk < 7) {
            const int d = (kk + 1) * 16;
            x0 = *(const float2*)(qrowA + d);
            x1 = *(const float2*)(qrowB + d);
            x2 = *(const float2*)(qrowA + d + 8);
            x3 = *(const float2*)(qrowB + d + 8);
        }
        #pragma unroll
        for (int nt2 = 0; nt2 < 4; nt2++) {
            uint32_t bb[4];
            ldsm4(bb, bK + nt2 * (16 * RSB) + kk * 32);
            mma16816(s[2*nt2],   a, bb);
            mma16816(s[2*nt2+1], a, bb + 2);
        }
    }

    // ---- softmax in C-fragment layout (rows lane/4 and lane/4+8) ----
    float mlo = -3.0e38f, mhi = -3.0e38f;
    #pragma unroll
    for (int nt = 0; nt < 8; nt++) {
        #pragma unroll
        for (int j = 0; j < 4; j++) {
            int col = nt * 8 + q * 2 + (j & 1);
            if (col >= kvlen) s[nt][j] = -3.0e38f;
        }
        mlo = fmaxf(mlo, fmaxf(s[nt][0], s[nt][1]));
        mhi = fmaxf(mhi, fmaxf(s[nt][2], s[nt][3]));
    }
    mlo = fmaxf(mlo, __shfl_xor_sync(0xffffffffu, mlo, 1));
    mlo = fmaxf(mlo, __shfl_xor_sync(0xffffffffu, mlo, 2));
    mhi = fmaxf(mhi, __shfl_xor_sync(0xffffffffu, mhi, 1));
    mhi = fmaxf(mhi, __shfl_xor_sync(0xffffffffu, mhi, 2));

    float slo = 0.0f, shi = 0.0f;
    #pragma unroll
    for (int nt = 0; nt < 8; nt++) {
        s[nt][0] = __expf(s[nt][0] - mlo);
        s[nt][1] = __expf(s[nt][1] - mlo);
        s[nt][2] = __expf(s[nt][2] - mhi);
        s[nt][3] = __expf(s[nt][3] - mhi);
        slo += s[nt][0] + s[nt][1];
        shi += s[nt][2] + s[nt][3];
    }
    slo += __shfl_xor_sync(0xffffffffu, slo, 1);
    slo += __shfl_xor_sync(0xffffffffu, slo, 2);
    shi += __shfl_xor_sync(0xffffffffu, shi, 1);
    shi += __shfl_xor_sync(0xffffffffu, shi, 2);
    const float invlo = 1.0f / slo;
    const float invhi = 1.0f / shi;

    // ---- P (unnormalized) -> fp16 A-fragments (C layout == A layout) ----
    uint32_t p[4][4];
    #pragma unroll
    for (int kt = 0; kt < 4; kt++) {
        p[kt][0] = h2(s[2*kt][0],   s[2*kt][1]);
        p[kt][1] = h2(s[2*kt][2],   s[2*kt][3]);
        p[kt][2] = h2(s[2*kt+1][0], s[2*kt+1][1]);
        p[kt][3] = h2(s[2*kt+1][2], s[2*kt+1][3]);
    }

    // ---- phase 2: V -> fp16, overwriting the (dead) K tile ----
    __syncthreads();   // all warps done reading K
    #pragma unroll 4
    for (int r = w; r < 64; r += 4) {
        const float4* src = (const float4*)(qkv + ((size_t)(b * 64 + r) * 32 + h) * 384);
        float4 v4 = src[64 + lane];
        *(uint2*)(smem + r * RSB + lane * 8) = make_uint2(h2(v4.x, v4.y), h2(v4.z, v4.w));
    }
    __syncthreads();

    // ---- O = P @ V in two 64-dim halves ----
    // B-frag (V, trans): key (lane&7)+((lane&8)?8:0), 8-dim half via lane bit4
    const uint32_t bV = sb + (uint32_t)((((lane & 7) + ((lane & 8) ? 8 : 0)) * RSB) + ((lane & 16) ? 16 : 0));
    float* o0 = out + ((size_t)(b * 64 + ra) * 32 + h) * 128 + q * 2;
    float* o1 = out + ((size_t)(b * 64 + ra + 8) * 32 + h) * 128 + q * 2;

    #pragma unroll
    for (int hd = 0; hd < 2; hd++) {
        float o[8][4];
        #pragma unroll
        for (int nt = 0; nt < 8; nt++)
            #pragma unroll
            for (int j = 0; j < 4; j++) o[nt][j] = 0.0f;

        #pragma unroll
        for (int kt = 0; kt < 4; kt++) {
            #pragma unroll
            for (int nt2 = 0; nt2 < 4; nt2++) {
                uint32_t bb[4];
                ldsm4t(bb, bV + (uint32_t)(kt * (16 * RSB) + hd * 128 + nt2 * 32));
                mma16816(o[2*nt2],   p[kt], bb);
                mma16816(o[2*nt2+1], p[kt], bb + 2);
            }
        }
        #pragma unroll
        for (int nt = 0; nt < 8; nt++) {
            *(float2*)(o0 + hd * 64 + nt * 8) = make_float2(o[nt][0] * invlo, o[nt][1] * invlo);
            *(float2*)(o1 + hd * 64 + nt * 8) = make_float2(o[nt][2] * invhi, o[nt][3] * invhi);
        }
    }
}

extern "C" void kernel_launch(void* const* d_in, const int* in_sizes, int n_in,
                              void* d_out, int out_size)
{
    const float* qkv  = (const float*)d_in[0];
    const int*   kvlp = (n_in > 1) ? (const int*)d_in[1] : nullptr;
    float*       out  = (float*)d_out;

    cudaFuncSetAttribute(attn_hmma, cudaFuncAttributeMaxDynamicSharedMemorySize, SMEM_BYTES);
    attn_hmma<<<128 * 32, 128, SMEM_BYTES>>>(qkv, kvlp, out);
}